// round 16
// baseline (speedup 1.0000x reference)
#include <cuda_runtime.h>
#include <cuda_bf16.h>
#include <math.h>
#include <stdint.h>

// ---------------- problem constants ----------------
constexpr int R    = 4096;
constexpr int D    = 4096;
constexpr int C    = 20;
constexpr int NC   = 21;
constexpr float IMG_W = 1216.0f;
constexpr float IMG_H = 800.0f;
constexpr float SCORE_THRESH = 0.05f;
constexpr float NMS_THRESH   = 0.5f;
constexpr int TOPK = 100;
constexpr int NPAD = 48;

// ---------------- mma GEMM config ----------------
constexpr int BMG = 128;
constexpr int GRB = R / BMG;             // 32 row blocks
constexpr int GKS = 8;                   // K split
constexpr int KPB = D / GKS;             // 512
constexpr int KC  = 64;
constexpr int NCH = KPB / KC;            // 8
constexpr int GTH = 256;                 // 8 warps
constexpr int NBLK = GRB * GKS;          // 256 blocks

// smem layout (bytes)
// A: warp-private double buffer: 8 warps x 2 bufs x 16 rows x 144B
constexpr int RS_A   = 144;              // 64 bf16 = 128B + 16 pad
constexpr int BUF_A  = 16 * RS_A;        // 2304
constexpr int WARP_A = 2 * BUF_A;        // 4608
constexpr int SM_A   = 0;
constexpr int SM_B   = 8 * WARP_A;       // 36864
// B: full 512-K slice, 48 rows x 1024B (+16 pad)
constexpr int RS_B   = 1040;
constexpr int SM_TOTAL = SM_B + NPAD * RS_B;   // 86784

// tail smem overlay
struct TailSmem {
    float scol[8][NC];
    float scls[64][NC];
    float sdet[64][C];
    float bv[256];
    int   bfi[256];
    int   bps[256];
    int   scnt;
    int   s_base;
    int   s_woff[8];
    float s_cs;
    int   s_last;
    unsigned char ssupp[R];
};
static_assert(sizeof(TailSmem) <= SM_TOTAL, "tail overlay too big");

// ---------------- device scratch ----------------
__device__ float g_part[GKS][R * NPAD];
__device__ float g_preT[C * R];
__device__ float g_colpart[64][NC];
__device__ float4 g_bclip[R];
__device__ float g_kept[R * C];
__device__ int   g_ncand;
__device__ int   g_cnt3, g_cnt4;
__device__ int   g_cntrb[GRB];           // per-row-block GEMM completion
__device__ float g_cand_val[R * C];
__device__ int   g_cand_idx[R * C];
__device__ int   g_sidx[C][R];
__device__ float g_sval[C][R];
__device__ int   g_sorder[C][R];

// ---------------- helpers ----------------
__device__ __forceinline__ uint32_t pack_bf2(float lo, float hi) {
    __nv_bfloat162 h = __floats2bfloat162_rn(lo, hi);
    return *reinterpret_cast<uint32_t*>(&h);
}
__device__ __forceinline__ uint32_t smem_u32(const void* p) {
    uint32_t a;
    asm("{ .reg .u64 t; cvta.to.shared.u64 t, %1; cvt.u32.u64 %0, t; }" : "=r"(a) : "l"(p));
    return a;
}
__device__ __forceinline__ void mma_bf16(float* c, uint32_t a0, uint32_t a1,
                                         uint32_t a2, uint32_t a3,
                                         uint32_t b0, uint32_t b1) {
    asm volatile(
        "mma.sync.aligned.m16n8k16.row.col.f32.bf16.bf16.f32 "
        "{%0,%1,%2,%3}, {%4,%5,%6,%7}, {%8,%9}, {%0,%1,%2,%3};"
        : "+f"(c[0]), "+f"(c[1]), "+f"(c[2]), "+f"(c[3])
        : "r"(a0), "r"(a1), "r"(a2), "r"(a3), "r"(b0), "r"(b1));
}
__device__ __forceinline__ void ldsm_x4(uint32_t& r0, uint32_t& r1,
                                        uint32_t& r2, uint32_t& r3, uint32_t addr) {
    asm volatile("ldmatrix.sync.aligned.m8n8.x4.shared.b16 {%0,%1,%2,%3}, [%4];"
                 : "=r"(r0), "=r"(r1), "=r"(r2), "=r"(r3) : "r"(addr));
}
__device__ __forceinline__ float iou_f(float4 a, float4 b) {
    float areaA = (a.z - a.x) * (a.w - a.y);
    float areaB = (b.z - b.x) * (b.w - b.y);
    float lx = fmaxf(a.x, b.x), ly = fmaxf(a.y, b.y);
    float rx = fminf(a.z, b.z), ry = fminf(a.w, b.w);
    float w = fmaxf(rx - lx, 0.f), h = fmaxf(ry - ly, 0.f);
    float inter = w * h;
    return inter / (areaA + areaB - inter + 1e-9f);
}

// ---------------- ONE persistent kernel: gemm + tail ----------------
__global__ __launch_bounds__(GTH, 2) void k_all(const float* __restrict__ x,
                                                const float* __restrict__ Wc,
                                                const float* __restrict__ Wd,
                                                const float* __restrict__ b_cls,
                                                const float* __restrict__ b_det,
                                                const float* __restrict__ boxes,
                                                float* __restrict__ out) {
    extern __shared__ char smem[];
    const uint32_t sb = smem_u32(smem);
    const int tid  = threadIdx.x;
    const int bid  = blockIdx.x;
    const int lane = tid & 31;
    const int w    = tid >> 5;
    const int g    = lane >> 2;
    const int t    = lane & 3;
    const int rb = bid & 31;
    const int ks = bid >> 5;
    const int row0  = rb * BMG;
    const int kbase = ks * KPB;

    float acc[6][4];
#pragma unroll
    for (int nt = 0; nt < 6; nt++)
#pragma unroll
        for (int j = 0; j < 4; j++) acc[nt][j] = 0.f;

    // warp-private A path: warp w owns rows row0+16w .. +15
    const int quad = lane & 15;
    const uint32_t warpA = sb + SM_A + w * WARP_A;
    float4 xr0[8], xr1[8];

    auto ldgA = [&](int ch, float4* xr) {
        const float* src = x + (size_t)(row0 + w * 16 + (lane >> 4)) * D
                             + kbase + ch * KC + quad * 4;
#pragma unroll
        for (int it = 0; it < 8; it++)
            xr[it] = *reinterpret_cast<const float4*>(src + (size_t)(2 * it) * D);
    };
    auto stsA = [&](int buf, const float4* xr) {
        const uint32_t ab = warpA + buf * BUF_A + (lane >> 4) * RS_A + quad * 8;
#pragma unroll
        for (int it = 0; it < 8; it++) {
            uint2 v = make_uint2(pack_bf2(xr[it].x, xr[it].y),
                                 pack_bf2(xr[it].z, xr[it].w));
            asm volatile("st.shared.v2.b32 [%0], {%1, %2};"
                         :: "r"(ab + 2 * it * RS_A), "r"(v.x), "r"(v.y));
        }
    };
    // B: load this block's W f32 slice directly (L2-resident), convert to bf16 smem
    auto ldB = [&]() {
        const uint32_t bb = sb + SM_B;
#pragma unroll 8
        for (int it = 0; it < 96; it++) {
            int q = it * GTH + tid;             // 0..24575 = 512 k x 48 n
            int k = q / 48;
            int n = q - k * 48;
            float v = 0.f;
            if (n < 21)      v = Wc[(size_t)(kbase + k) * NC + n];
            else if (n < 42) v = Wd[(size_t)(kbase + k) * NC + (n - 21)];
            __nv_bfloat16 h = __float2bfloat16(v);
            unsigned short hs = *reinterpret_cast<unsigned short*>(&h);
            asm volatile("st.shared.b16 [%0], %1;"
                         :: "r"(bb + n * RS_B + k * 2), "h"(hs));
        }
    };

    ldgA(0, xr0);   // x prefetch in flight while B converts
    ldB();
    __syncthreads();           // B resident + visible; LAST sync before mainloop

    // fragment lane addressing (verified R11/R15 mapping)
    const int part = lane >> 3;
    const int r8   = lane & 7;
    const uint32_t a_frag = warpA + ((part & 1) * 8 + r8) * RS_A + (part >> 1) * 16;
    const uint32_t b_frag = sb + SM_B + ((part >> 1) * 8 + r8) * RS_B + (part & 1) * 16;

    stsA(0, xr0);
    ldgA(1, xr1);

    for (int ch = 0; ch < NCH; ch++) {
        const int buf = ch & 1;
        if (ch + 2 < NCH) ldgA(ch + 2, buf ? xr1 : xr0);   // bank of ch (consumed)
        const uint32_t ab = a_frag + buf * BUF_A;
        const uint32_t bb = b_frag + ch * 128;
#pragma unroll
        for (int kq = 0; kq < 4; kq++) {
            uint32_t a0, a1, a2, a3;
            ldsm_x4(a0, a1, a2, a3, ab + kq * 32);
#pragma unroll
            for (int p = 0; p < 3; p++) {
                uint32_t b0, b1, b2, b3;
                ldsm_x4(b0, b1, b2, b3, bb + p * 16 * RS_B + kq * 32);
                mma_bf16(acc[2 * p + 0], a0, a1, a2, a3, b0, b1);
                mma_bf16(acc[2 * p + 1], a0, a1, a2, a3, b2, b3);
            }
        }
        if (ch + 1 < NCH) stsA(buf ^ 1, (buf ^ 1) ? xr1 : xr0);
    }

    {
        float* dst = &g_part[ks][0];
        int row = row0 + w * 16 + g;
#pragma unroll
        for (int nt = 0; nt < 6; nt++) {
            int col = nt * 8 + 2 * t;
            *reinterpret_cast<float2*>(&dst[(size_t)row * NPAD + col]) =
                make_float2(acc[nt][0], acc[nt][1]);
            *reinterpret_cast<float2*>(&dst[(size_t)(row + 8) * NPAD + col]) =
                make_float2(acc[nt][2], acc[nt][3]);
        }
    }
    __syncthreads();           // all warps' partials issued before the arrive

    // ---- per-row-block completion: tail waits only on its 8 producers ----
    if (tid == 0) {
        __threadfence();
        atomicAdd(&g_cntrb[rb], 1);
    }
    if (bid >= 64) return;
    if (tid == 0) {
        while (atomicAdd(&g_cntrb[bid >> 1], 0) < GKS) {}
    }
    __syncthreads();
    __threadfence();

    // ---- tail phase 1 (blocks 0..63) ----
    TailSmem* ts = reinterpret_cast<TailSmem*>(smem);
    const int row0t = bid * 64;

    if (tid < 8 * NC) ts->scol[tid / NC][tid % NC] = 0.f;
    __syncthreads();
    for (int q = tid; q < 64 * 2 * NC; q += 256) {
        int lr  = q / (2 * NC);
        int c   = q % (2 * NC);
        int row = row0t + lr;
        float s = 0.f;
#pragma unroll
        for (int k2 = 0; k2 < GKS; k2++) s += g_part[k2][(size_t)row * NPAD + c];
        if (c < NC) {
            ts->scls[lr][c] = s + b_cls[c];
        } else {
            int cd = c - NC;
            float e = expf(s + b_det[cd]);
            if (cd < C) ts->sdet[lr][cd] = e;
            ts->scol[w][cd] += e;   // 32 consecutive q -> distinct c (42 > 32)
        }
    }
    for (int q = tid; q < 64 * C; q += 256) g_kept[row0t * C + q] = 0.f;
    if (tid < 64) {
        int row = row0t + tid;
        float4 b = reinterpret_cast<const float4*>(boxes)[row];
        g_bclip[row] = make_float4(fminf(fmaxf(b.x, 0.f), IMG_W),
                                   fminf(fmaxf(b.y, 0.f), IMG_H),
                                   fminf(fmaxf(b.z, 0.f), IMG_W),
                                   fminf(fmaxf(b.w, 0.f), IMG_H));
    }
    if (bid == 0 && tid == 0) g_ncand = 0;
    __syncthreads();
    if (tid < NC) {
        float s = 0.f;
#pragma unroll
        for (int w2 = 0; w2 < 8; w2++) s += ts->scol[w2][tid];
        g_colpart[bid][tid] = s;
    }
#pragma unroll
    for (int rr = 0; rr < 8; rr++) {
        int lr = rr * 8 + w;
        float e = (lane < NC) ? expf(ts->scls[lr][lane]) : 0.f;
        float s = e;
#pragma unroll
        for (int o = 16; o > 0; o >>= 1) s += __shfl_xor_sync(0xffffffffu, s, o);
        float inv = 1.f / s;
        if (lane < C) g_preT[lane * R + row0t + lr] = e * inv * ts->sdet[lr][lane];
    }
    __syncthreads();

    // ---- barrier 3: tail phase 1 complete (64 blocks) ----
    if (tid == 0) {
        __threadfence();
        atomicAdd(&g_cnt3, 1);
    }
    if (bid >= C) return;
    if (tid == 0) {
        while (atomicAdd(&g_cnt3, 0) < 64) {}
    }
    __syncthreads();
    __threadfence();

    // ---- phase 2: per-class NMS ----
    const int cls = bid;
    if (tid < 32) {
        float s = g_colpart[tid][cls] + g_colpart[tid + 32][cls];
#pragma unroll
        for (int o = 16; o > 0; o >>= 1) s += __shfl_xor_sync(0xffffffffu, s, o);
        if (tid == 0) { ts->s_cs = 1.f / s; ts->scnt = 0; }
    }
    __syncthreads();
    const float ics = ts->s_cs;

    for (int r = tid; r < R; r += 256) {
        float v = g_preT[cls * R + r] * ics;
        if (v > SCORE_THRESH) {
            int p = atomicAdd(&ts->scnt, 1);
            g_sidx[cls][p] = r;
            g_sval[cls][p] = v;
        }
    }
    __syncthreads();
    const int m = ts->scnt;
    if (m > 0) {
        for (int i = tid; i < m; i += 256) {
            float vi = g_sval[cls][i];
            int   ri = g_sidx[cls][i];
            int rank = 0;
            for (int j = 0; j < m; j++) {
                float vj = g_sval[cls][j];
                int   rj = g_sidx[cls][j];
                if (vj > vi || (vj == vi && rj < ri)) rank++;
            }
            g_sorder[cls][rank] = i;
        }
        for (int q = tid; q < m; q += 256) ts->ssupp[q] = 0;
        __syncthreads();
        for (int pos = 0; pos < m; pos++) {
            if (!ts->ssupp[pos]) {
                int   i = g_sorder[cls][pos];
                int   r = g_sidx[cls][i];
                float v = g_sval[cls][i];
                if (tid == 0) {
                    g_kept[r * C + cls] = v;
                    int p = atomicAdd(&g_ncand, 1);
                    g_cand_val[p] = v;
                    g_cand_idx[p] = r * C + cls;
                }
                float4 bi = g_bclip[r];
                for (int q = pos + 1 + tid; q < m; q += 256) {
                    if (!ts->ssupp[q]) {
                        int j = g_sorder[cls][q];
                        float4 bj = g_bclip[g_sidx[cls][j]];
                        if (iou_f(bi, bj) > NMS_THRESH) ts->ssupp[q] = 1;
                    }
                }
            }
            __syncthreads();
        }
    }

    // ---- barrier 4: last NMS block runs the final top-k ----
    if (tid == 0) {
        __threadfence();
        ts->s_last = (atomicAdd(&g_cnt4, 1) == C - 1) ? 1 : 0;
    }
    __syncthreads();
    if (!ts->s_last) return;
    if (tid == 0) {
        g_cnt3 = 0; g_cnt4 = 0;
#pragma unroll
        for (int i = 0; i < GRB; i++) g_cntrb[i] = 0;
    }
    __threadfence();

    int n = g_ncand;
    if (n > R * C) n = R * C;
    int take = n < TOPK ? n : TOPK;
    for (int round = 0; round < take; round++) {
        float best = -2.f; int bestfi = 0x7fffffff; int bestp = -1;
        for (int p = tid; p < n; p += 256) {
            float v = g_cand_val[p];
            if (v < 0.f) continue;
            int fi = g_cand_idx[p];
            if (v > best || (v == best && fi < bestfi)) {
                best = v; bestfi = fi; bestp = p;
            }
        }
        ts->bv[tid] = best; ts->bfi[tid] = bestfi; ts->bps[tid] = bestp;
        __syncthreads();
        for (int s = 128; s > 0; s >>= 1) {
            if (tid < s) {
                if (ts->bv[tid + s] > ts->bv[tid] ||
                    (ts->bv[tid + s] == ts->bv[tid] && ts->bfi[tid + s] < ts->bfi[tid])) {
                    ts->bv[tid] = ts->bv[tid + s];
                    ts->bfi[tid] = ts->bfi[tid + s];
                    ts->bps[tid] = ts->bps[tid + s];
                }
            }
            __syncthreads();
        }
        if (tid == 0) {
            int fi = ts->bfi[0];
            int prop = fi / C, cl = fi % C;
            float4 b = g_bclip[prop];
            out[round] = ts->bv[0];
            out[TOPK + round * 4 + 0] = b.x;
            out[TOPK + round * 4 + 1] = b.y;
            out[TOPK + round * 4 + 2] = b.z;
            out[TOPK + round * 4 + 3] = b.w;
            out[TOPK + TOPK * 4 + round] = (float)cl;
            g_cand_val[ts->bps[0]] = -1.f;
        }
        __syncthreads();
    }
    if (tid == 0) ts->s_base = take;
    __syncthreads();
    for (int chunk = 0; chunk < R * C; chunk += 256) {
        if (ts->s_base >= TOPK) break;
        int e = chunk + tid;
        bool f = (g_kept[e] == 0.f);
        unsigned bal = __ballot_sync(0xffffffffu, f);
        if ((tid & 31) == 0) ts->s_woff[tid >> 5] = __popc(bal);
        __syncthreads();
        int pre = 0;
#pragma unroll
        for (int w2 = 0; w2 < 8; w2++)
            if (w2 < (tid >> 5)) pre += ts->s_woff[w2];
        int rank = pre + __popc(bal & ((1u << (tid & 31)) - 1u));
        int slot = ts->s_base + rank;
        if (f && slot < TOPK) {
            int prop = e / C, cl = e % C;
            float4 b = g_bclip[prop];
            out[slot] = 0.f;
            out[TOPK + slot * 4 + 0] = b.x;
            out[TOPK + slot * 4 + 1] = b.y;
            out[TOPK + slot * 4 + 2] = b.z;
            out[TOPK + slot * 4 + 3] = b.w;
            out[TOPK + TOPK * 4 + slot] = (float)cl;
        }
        __syncthreads();
        if (tid == 0) {
            int tot = 0;
#pragma unroll
            for (int w2 = 0; w2 < 8; w2++) tot += ts->s_woff[w2];
            ts->s_base += tot;
            if (ts->s_base > TOPK) ts->s_base = TOPK;
        }
        __syncthreads();
    }
}

extern "C" void kernel_launch(void* const* d_in, const int* in_sizes, int n_in,
                              void* d_out, int out_size) {
    const float* x     = (const float*)d_in[0];
    const float* boxes = (const float*)d_in[1];
    const float* W_cls = (const float*)d_in[2];
    const float* b_cls = (const float*)d_in[3];
    const float* W_det = (const float*)d_in[4];
    const float* b_det = (const float*)d_in[5];
    float* out = (float*)d_out;

    static bool attr_set = false;
    if (!attr_set) {
        cudaFuncSetAttribute(k_all, cudaFuncAttributeMaxDynamicSharedMemorySize,
                             SM_TOTAL);
        attr_set = true;
    }

    k_all<<<NBLK, GTH, SM_TOTAL>>>(x, W_cls, W_det, b_cls, b_det, boxes, out);
}

// round 17
// speedup vs baseline: 1.7029x; 1.7029x over previous
#include <cuda_runtime.h>
#include <cuda_bf16.h>
#include <math.h>
#include <stdint.h>

// ---------------- problem constants ----------------
constexpr int R    = 4096;
constexpr int D    = 4096;
constexpr int C    = 20;
constexpr int NC   = 21;
constexpr float IMG_W = 1216.0f;
constexpr float IMG_H = 800.0f;
constexpr float SCORE_THRESH = 0.05f;
constexpr float NMS_THRESH   = 0.5f;
constexpr int TOPK = 100;
constexpr int NPAD = 48;

// ---------------- mma GEMM config ----------------
constexpr int BMG = 128;
constexpr int GRB = R / BMG;             // 32 row blocks
constexpr int GKS = 8;                   // K split
constexpr int KPB = D / GKS;             // 512
constexpr int KC  = 64;
constexpr int NCH = KPB / KC;            // 8
constexpr int GTH = 256;                 // 8 warps
constexpr int NBLK = GRB * GKS;          // 256 blocks

// smem layout (bytes)
// A: warp-private double buffer: 8 warps x 2 bufs x 16 rows x 144B
constexpr int RS_A   = 144;              // 64 bf16 = 128B + 16 pad
constexpr int BUF_A  = 16 * RS_A;        // 2304
constexpr int WARP_A = 2 * BUF_A;        // 4608
constexpr int SM_A   = 0;
constexpr int SM_B   = 8 * WARP_A;       // 36864
// B: full 512-K slice, 48 rows x 1024B (+16 pad)
constexpr int RS_B   = 1040;
constexpr int SM_TOTAL = SM_B + NPAD * RS_B;   // 86784

// tail smem overlay
struct TailSmem {
    float scol[8][NC];
    float scls[64][NC];
    float sdet[64][C];
    float bv[256];
    int   bfi[256];
    int   bps[256];
    int   scnt;
    int   s_base;
    int   s_woff[8];
    float s_cs;
    int   s_last;
    unsigned char ssupp[R];
};
static_assert(sizeof(TailSmem) <= SM_TOTAL, "tail overlay too big");

// ---------------- device scratch ----------------
__device__ __nv_bfloat16 g_WbfT[NPAD * D];   // W transposed+padded bf16, [n][k]
__device__ float g_part[GKS][R * NPAD];
__device__ float g_preT[C * R];
__device__ float g_colpart[64][NC];
__device__ float4 g_bclip[R];
__device__ float g_kept[R * C];
__device__ int   g_ncand;
__device__ int   g_cnt1, g_cnt3, g_cnt4;
__device__ int   g_cntrb[GRB];           // per-row-block GEMM completion
__device__ float g_cand_val[R * C];
__device__ int   g_cand_idx[R * C];
__device__ int   g_sidx[C][R];
__device__ float g_sval[C][R];
__device__ int   g_sorder[C][R];

// ---------------- helpers ----------------
__device__ __forceinline__ uint32_t pack_bf2(float lo, float hi) {
    __nv_bfloat162 h = __floats2bfloat162_rn(lo, hi);
    return *reinterpret_cast<uint32_t*>(&h);
}
__device__ __forceinline__ uint32_t smem_u32(const void* p) {
    uint32_t a;
    asm("{ .reg .u64 t; cvta.to.shared.u64 t, %1; cvt.u32.u64 %0, t; }" : "=r"(a) : "l"(p));
    return a;
}
#define CP16(dst, src) \
    asm volatile("cp.async.ca.shared.global [%0], [%1], 16;" :: "r"(dst), "l"(src))
#define CP_COMMIT() asm volatile("cp.async.commit_group;" ::: "memory")
#define CP_WAIT0()  asm volatile("cp.async.wait_group 0;" ::: "memory")

__device__ __forceinline__ void mma_bf16(float* c, uint32_t a0, uint32_t a1,
                                         uint32_t a2, uint32_t a3,
                                         uint32_t b0, uint32_t b1) {
    asm volatile(
        "mma.sync.aligned.m16n8k16.row.col.f32.bf16.bf16.f32 "
        "{%0,%1,%2,%3}, {%4,%5,%6,%7}, {%8,%9}, {%0,%1,%2,%3};"
        : "+f"(c[0]), "+f"(c[1]), "+f"(c[2]), "+f"(c[3])
        : "r"(a0), "r"(a1), "r"(a2), "r"(a3), "r"(b0), "r"(b1));
}
__device__ __forceinline__ void ldsm_x4(uint32_t& r0, uint32_t& r1,
                                        uint32_t& r2, uint32_t& r3, uint32_t addr) {
    asm volatile("ldmatrix.sync.aligned.m8n8.x4.shared.b16 {%0,%1,%2,%3}, [%4];"
                 : "=r"(r0), "=r"(r1), "=r"(r2), "=r"(r3) : "r"(addr));
}
__device__ __forceinline__ float iou_f(float4 a, float4 b) {
    float areaA = (a.z - a.x) * (a.w - a.y);
    float areaB = (b.z - b.x) * (b.w - b.y);
    float lx = fmaxf(a.x, b.x), ly = fmaxf(a.y, b.y);
    float rx = fminf(a.z, b.z), ry = fminf(a.w, b.w);
    float w = fmaxf(rx - lx, 0.f), h = fmaxf(ry - ly, 0.f);
    float inter = w * h;
    return inter / (areaA + areaB - inter + 1e-9f);
}

// ---------------- ONE persistent kernel: prep + gemm + tail ----------------
__global__ __launch_bounds__(GTH, 2) void k_all(const float* __restrict__ x,
                                                const float* __restrict__ Wc,
                                                const float* __restrict__ Wd,
                                                const float* __restrict__ b_cls,
                                                const float* __restrict__ b_det,
                                                const float* __restrict__ boxes,
                                                float* __restrict__ out) {
    extern __shared__ char smem[];
    const uint32_t sb = smem_u32(smem);
    const int tid  = threadIdx.x;
    const int bid  = blockIdx.x;
    const int lane = tid & 31;
    const int w    = tid >> 5;
    const int g    = lane >> 2;
    const int t    = lane & 3;
    const int rb = bid & 31;
    const int ks = bid >> 5;
    const int row0  = rb * BMG;
    const int kbase = ks * KPB;

    // ---- phase 0: cooperative W -> bf16 transposed (16 k-rows per block) ----
    {
        const int b16 = bid * 16;
        if (tid < 16 * NC) {
            int kk = tid / NC, n = tid - (tid / NC) * NC;
            int k = b16 + kk;
            g_WbfT[(size_t)n * D + k]        = __float2bfloat16(Wc[(size_t)k * NC + n]);
            g_WbfT[(size_t)(NC + n) * D + k] = __float2bfloat16(Wd[(size_t)k * NC + n]);
        }
        if (tid < 48)
            reinterpret_cast<uint32_t*>(g_WbfT)[(42 * D) / 2 + bid * 48 + tid] = 0u;
    }

    float acc[6][4];
#pragma unroll
    for (int nt = 0; nt < 6; nt++)
#pragma unroll
        for (int j = 0; j < 4; j++) acc[nt][j] = 0.f;

    // warp-private A path: warp w owns rows row0+16w .. +15
    const int quad = lane & 15;
    const uint32_t warpA = sb + SM_A + w * WARP_A;
    float4 xr0[8], xr1[8];

    auto ldgA = [&](int ch, float4* xr) {
        const float* src = x + (size_t)(row0 + w * 16 + (lane >> 4)) * D
                             + kbase + ch * KC + quad * 4;
#pragma unroll
        for (int it = 0; it < 8; it++)
            xr[it] = *reinterpret_cast<const float4*>(src + (size_t)(2 * it) * D);
    };
    auto stsA = [&](int buf, const float4* xr) {
        const uint32_t ab = warpA + buf * BUF_A + (lane >> 4) * RS_A + quad * 8;
#pragma unroll
        for (int it = 0; it < 8; it++) {
            uint2 v = make_uint2(pack_bf2(xr[it].x, xr[it].y),
                                 pack_bf2(xr[it].z, xr[it].w));
            asm volatile("st.shared.v2.b32 [%0], {%1, %2};"
                         :: "r"(ab + 2 * it * RS_A), "r"(v.x), "r"(v.y));
        }
    };
    auto cpB = [&]() {
        const uint32_t bb = sb + SM_B;
#pragma unroll
        for (int it = 0; it < 12; it++) {
            int q = tid + it * GTH;                 // 3072 = 48 rows x 64 segs
            int nn = q >> 6, seg = q & 63;
            CP16(bb + nn * RS_B + seg * 16,
                 reinterpret_cast<const char*>(g_WbfT) +
                     ((size_t)nn * D + kbase) * 2 + seg * 16);
        }
    };

    ldgA(0, xr0);   // x prefetch in flight while barrier spins

    // ---- barrier 1: W conversion complete (all 256) ----
    if (tid == 0) {
        __threadfence();
        atomicAdd(&g_cnt1, 1);
        while (atomicAdd(&g_cnt1, 0) < NBLK) {}
    }
    __syncthreads();

    cpB(); CP_COMMIT();
    CP_WAIT0();
    __syncthreads();           // B resident + visible; LAST sync before mainloop

    // fragment lane addressing (verified R11/R15 mapping)
    const int part = lane >> 3;
    const int r8   = lane & 7;
    const uint32_t a_frag = warpA + ((part & 1) * 8 + r8) * RS_A + (part >> 1) * 16;
    const uint32_t b_frag = sb + SM_B + ((part >> 1) * 8 + r8) * RS_B + (part & 1) * 16;

    stsA(0, xr0);
    ldgA(1, xr1);

    for (int ch = 0; ch < NCH; ch++) {
        const int buf = ch & 1;
        if (ch + 2 < NCH) ldgA(ch + 2, buf ? xr1 : xr0);   // bank of ch (consumed)
        const uint32_t ab = a_frag + buf * BUF_A;
        const uint32_t bb = b_frag + ch * 128;
#pragma unroll
        for (int kq = 0; kq < 4; kq++) {
            uint32_t a0, a1, a2, a3;
            ldsm_x4(a0, a1, a2, a3, ab + kq * 32);
#pragma unroll
            for (int p = 0; p < 3; p++) {
                uint32_t b0, b1, b2, b3;
                ldsm_x4(b0, b1, b2, b3, bb + p * 16 * RS_B + kq * 32);
                mma_bf16(acc[2 * p + 0], a0, a1, a2, a3, b0, b1);
                mma_bf16(acc[2 * p + 1], a0, a1, a2, a3, b2, b3);
            }
        }
        if (ch + 1 < NCH) stsA(buf ^ 1, (buf ^ 1) ? xr1 : xr0);
    }

    {
        float* dst = &g_part[ks][0];
        int row = row0 + w * 16 + g;
#pragma unroll
        for (int nt = 0; nt < 6; nt++) {
            int col = nt * 8 + 2 * t;
            *reinterpret_cast<float2*>(&dst[(size_t)row * NPAD + col]) =
                make_float2(acc[nt][0], acc[nt][1]);
            *reinterpret_cast<float2*>(&dst[(size_t)(row + 8) * NPAD + col]) =
                make_float2(acc[nt][2], acc[nt][3]);
        }
    }
    __syncthreads();           // all warps' partials issued before the arrive

    // ---- per-row-block completion: tail waits only on its 8 producers ----
    if (tid == 0) {
        __threadfence();
        atomicAdd(&g_cntrb[rb], 1);
    }
    if (bid >= 64) return;
    if (tid == 0) {
        while (atomicAdd(&g_cntrb[bid >> 1], 0) < GKS) {}
    }
    __syncthreads();
    __threadfence();

    // ---- tail phase 1 (blocks 0..63) ----
    TailSmem* ts = reinterpret_cast<TailSmem*>(smem);
    const int row0t = bid * 64;

    if (tid < 8 * NC) ts->scol[tid / NC][tid % NC] = 0.f;
    __syncthreads();
    for (int q = tid; q < 64 * 2 * NC; q += 256) {
        int lr  = q / (2 * NC);
        int c   = q % (2 * NC);
        int row = row0t + lr;
        float s = 0.f;
#pragma unroll
        for (int k2 = 0; k2 < GKS; k2++) s += g_part[k2][(size_t)row * NPAD + c];
        if (c < NC) {
            ts->scls[lr][c] = s + b_cls[c];
        } else {
            int cd = c - NC;
            float e = expf(s + b_det[cd]);
            if (cd < C) ts->sdet[lr][cd] = e;
            ts->scol[w][cd] += e;   // 32 consecutive q -> distinct c (42 > 32)
        }
    }
    for (int q = tid; q < 64 * C; q += 256) g_kept[row0t * C + q] = 0.f;
    if (tid < 64) {
        int row = row0t + tid;
        float4 b = reinterpret_cast<const float4*>(boxes)[row];
        g_bclip[row] = make_float4(fminf(fmaxf(b.x, 0.f), IMG_W),
                                   fminf(fmaxf(b.y, 0.f), IMG_H),
                                   fminf(fmaxf(b.z, 0.f), IMG_W),
                                   fminf(fmaxf(b.w, 0.f), IMG_H));
    }
    if (bid == 0 && tid == 0) g_ncand = 0;
    __syncthreads();
    if (tid < NC) {
        float s = 0.f;
#pragma unroll
        for (int w2 = 0; w2 < 8; w2++) s += ts->scol[w2][tid];
        g_colpart[bid][tid] = s;
    }
#pragma unroll
    for (int rr = 0; rr < 8; rr++) {
        int lr = rr * 8 + w;
        float e = (lane < NC) ? expf(ts->scls[lr][lane]) : 0.f;
        float s = e;
#pragma unroll
        for (int o = 16; o > 0; o >>= 1) s += __shfl_xor_sync(0xffffffffu, s, o);
        float inv = 1.f / s;
        if (lane < C) g_preT[lane * R + row0t + lr] = e * inv * ts->sdet[lr][lane];
    }
    __syncthreads();

    // ---- barrier 3: tail phase 1 complete (64 blocks) ----
    if (tid == 0) {
        __threadfence();
        atomicAdd(&g_cnt3, 1);
    }
    if (bid >= C) return;
    if (tid == 0) {
        while (atomicAdd(&g_cnt3, 0) < 64) {}
    }
    __syncthreads();
    __threadfence();

    // ---- phase 2: per-class NMS ----
    const int cls = bid;
    if (tid < 32) {
        float s = g_colpart[tid][cls] + g_colpart[tid + 32][cls];
#pragma unroll
        for (int o = 16; o > 0; o >>= 1) s += __shfl_xor_sync(0xffffffffu, s, o);
        if (tid == 0) { ts->s_cs = 1.f / s; ts->scnt = 0; }
    }
    __syncthreads();
    const float ics = ts->s_cs;

    for (int r = tid; r < R; r += 256) {
        float v = g_preT[cls * R + r] * ics;
        if (v > SCORE_THRESH) {
            int p = atomicAdd(&ts->scnt, 1);
            g_sidx[cls][p] = r;
            g_sval[cls][p] = v;
        }
    }
    __syncthreads();
    const int m = ts->scnt;
    if (m > 0) {
        for (int i = tid; i < m; i += 256) {
            float vi = g_sval[cls][i];
            int   ri = g_sidx[cls][i];
            int rank = 0;
            for (int j = 0; j < m; j++) {
                float vj = g_sval[cls][j];
                int   rj = g_sidx[cls][j];
                if (vj > vi || (vj == vi && rj < ri)) rank++;
            }
            g_sorder[cls][rank] = i;
        }
        for (int q = tid; q < m; q += 256) ts->ssupp[q] = 0;
        __syncthreads();
        for (int pos = 0; pos < m; pos++) {
            if (!ts->ssupp[pos]) {
                int   i = g_sorder[cls][pos];
                int   r = g_sidx[cls][i];
                float v = g_sval[cls][i];
                if (tid == 0) {
                    g_kept[r * C + cls] = v;
                    int p = atomicAdd(&g_ncand, 1);
                    g_cand_val[p] = v;
                    g_cand_idx[p] = r * C + cls;
                }
                float4 bi = g_bclip[r];
                for (int q = pos + 1 + tid; q < m; q += 256) {
                    if (!ts->ssupp[q]) {
                        int j = g_sorder[cls][q];
                        float4 bj = g_bclip[g_sidx[cls][j]];
                        if (iou_f(bi, bj) > NMS_THRESH) ts->ssupp[q] = 1;
                    }
                }
            }
            __syncthreads();
        }
    }

    // ---- barrier 4: last NMS block runs the final top-k ----
    if (tid == 0) {
        __threadfence();
        ts->s_last = (atomicAdd(&g_cnt4, 1) == C - 1) ? 1 : 0;
    }
    __syncthreads();
    if (!ts->s_last) return;
    if (tid == 0) {
        g_cnt1 = 0; g_cnt3 = 0; g_cnt4 = 0;
#pragma unroll
        for (int i = 0; i < GRB; i++) g_cntrb[i] = 0;
    }
    __threadfence();

    int n = g_ncand;
    if (n > R * C) n = R * C;
    int take = n < TOPK ? n : TOPK;
    for (int round = 0; round < take; round++) {
        float best = -2.f; int bestfi = 0x7fffffff; int bestp = -1;
        for (int p = tid; p < n; p += 256) {
            float v = g_cand_val[p];
            if (v < 0.f) continue;
            int fi = g_cand_idx[p];
            if (v > best || (v == best && fi < bestfi)) {
                best = v; bestfi = fi; bestp = p;
            }
        }
        ts->bv[tid] = best; ts->bfi[tid] = bestfi; ts->bps[tid] = bestp;
        __syncthreads();
        for (int s = 128; s > 0; s >>= 1) {
            if (tid < s) {
                if (ts->bv[tid + s] > ts->bv[tid] ||
                    (ts->bv[tid + s] == ts->bv[tid] && ts->bfi[tid + s] < ts->bfi[tid])) {
                    ts->bv[tid] = ts->bv[tid + s];
                    ts->bfi[tid] = ts->bfi[tid + s];
                    ts->bps[tid] = ts->bps[tid + s];
                }
            }
            __syncthreads();
        }
        if (tid == 0) {
            int fi = ts->bfi[0];
            int prop = fi / C, cl = fi % C;
            float4 b = g_bclip[prop];
            out[round] = ts->bv[0];
            out[TOPK + round * 4 + 0] = b.x;
            out[TOPK + round * 4 + 1] = b.y;
            out[TOPK + round * 4 + 2] = b.z;
            out[TOPK + round * 4 + 3] = b.w;
            out[TOPK + TOPK * 4 + round] = (float)cl;
            g_cand_val[ts->bps[0]] = -1.f;
        }
        __syncthreads();
    }
    if (tid == 0) ts->s_base = take;
    __syncthreads();
    for (int chunk = 0; chunk < R * C; chunk += 256) {
        if (ts->s_base >= TOPK) break;
        int e = chunk + tid;
        bool f = (g_kept[e] == 0.f);
        unsigned bal = __ballot_sync(0xffffffffu, f);
        if ((tid & 31) == 0) ts->s_woff[tid >> 5] = __popc(bal);
        __syncthreads();
        int pre = 0;
#pragma unroll
        for (int w2 = 0; w2 < 8; w2++)
            if (w2 < (tid >> 5)) pre += ts->s_woff[w2];
        int rank = pre + __popc(bal & ((1u << (tid & 31)) - 1u));
        int slot = ts->s_base + rank;
        if (f && slot < TOPK) {
            int prop = e / C, cl = e % C;
            float4 b = g_bclip[prop];
            out[slot] = 0.f;
            out[TOPK + slot * 4 + 0] = b.x;
            out[TOPK + slot * 4 + 1] = b.y;
            out[TOPK + slot * 4 + 2] = b.z;
            out[TOPK + slot * 4 + 3] = b.w;
            out[TOPK + TOPK * 4 + slot] = (float)cl;
        }
        __syncthreads();
        if (tid == 0) {
            int tot = 0;
#pragma unroll
            for (int w2 = 0; w2 < 8; w2++) tot += ts->s_woff[w2];
            ts->s_base += tot;
            if (ts->s_base > TOPK) ts->s_base = TOPK;
        }
        __syncthreads();
    }
}

extern "C" void kernel_launch(void* const* d_in, const int* in_sizes, int n_in,
                              void* d_out, int out_size) {
    const float* x     = (const float*)d_in[0];
    const float* boxes = (const float*)d_in[1];
    const float* W_cls = (const float*)d_in[2];
    const float* b_cls = (const float*)d_in[3];
    const float* W_det = (const float*)d_in[4];
    const float* b_det = (const float*)d_in[5];
    float* out = (float*)d_out;

    static bool attr_set = false;
    if (!attr_set) {
        cudaFuncSetAttribute(k_all, cudaFuncAttributeMaxDynamicSharedMemorySize,
                             SM_TOTAL);
        attr_set = true;
    }

    k_all<<<NBLK, GTH, SM_TOTAL>>>(x, W_cls, W_det, b_cls, b_det, boxes, out);
}